// round 3
// baseline (speedup 1.0000x reference)
#include <cuda_runtime.h>
#include <cstdint>

#define NFEAT 256
#define NHID 64
#define NEG_SLOPE 0.05f
#define MAX_N 100000
#define MAX_E 1600000

// ---------------- device scratch (no allocation allowed) ----------------
__device__ float g_Wh[(size_t)MAX_N * NHID];   // 25.6 MB
__device__ float g_si[MAX_N];
__device__ float g_sj[MAX_N];
__device__ float g_hsum[MAX_N];                // later holds reciprocal
__device__ float g_h[MAX_E];                   // 6.4 MB
__device__ int   g_idx64;                      // 1 if edge_index is int64

// ---------------- index helper: dtype-adaptive, clamped ----------------
__device__ __forceinline__ int load_idx(const void* ei, size_t pos, int is64, int M) {
    int v;
    if (is64) v = (int)((const long long*)ei)[pos];
    else      v = ((const int*)ei)[pos];
    // defensive clamp: never fault, surface errors as rel_err instead
    v = v < 0 ? 0 : (v >= M ? M - 1 : v);
    return v;
}

// ---------------- kernel -1: detect edge_index dtype ----------------
// If the buffer is int32, interpreting pairs as int64 gives v_lo + v_hi*2^32,
// which is >= M unless v_hi == 0 (prob 1e-5 per sample). 4096 samples -> exact.
__global__ void detect_kernel(const void* ei, int E, int M) {
    __shared__ int bad;
    if (threadIdx.x == 0) bad = 0;
    __syncthreads();
    const long long* p = (const long long*)ei;  // safe: covers min(buffer) bytes
    int stride = E / 4096 > 0 ? E / 4096 : 1;
    for (int i = threadIdx.x; i < 4096; i += blockDim.x) {
        size_t pos = (size_t)i * stride;
        if (pos < (size_t)E) {
            long long v = p[pos];
            if (v < 0 || v >= M) atomicOr(&bad, 1);
        }
    }
    __syncthreads();
    if (threadIdx.x == 0) g_idx64 = bad ? 0 : 1;
}

// ---------------- kernel 0: zero out-region + h_sum ----------------
__global__ void zero_kernel(float4* __restrict__ out, int M) {
    int i = blockIdx.x * blockDim.x + threadIdx.x;
    if (i < M * (NHID / 4)) out[i] = make_float4(0.f, 0.f, 0.f, 0.f);
    if (i < M) g_hsum[i] = 0.f;
}

// ---------------- kernel 1: Wh = x @ W_fc  (fp32 SMEM-tiled GEMM) -------
// BM=64, BN=64(full), BK=32, 256 threads, 4x4 micro-tile per thread.
__global__ void gemm_kernel(const float* __restrict__ x,
                            const float* __restrict__ W,
                            int M) {
    __shared__ float As[32][64];   // [k][m]  (A transposed)
    __shared__ float Bs[32][64];   // [k][n]

    const int tid = threadIdx.x;
    const int m0  = blockIdx.x * 64;
    const int ty  = tid >> 4;     // 0..15 -> row group
    const int tx  = tid & 15;     // 0..15 -> col group

    float acc[4][4];
#pragma unroll
    for (int i = 0; i < 4; i++)
#pragma unroll
        for (int j = 0; j < 4; j++) acc[i][j] = 0.f;

    for (int k0 = 0; k0 < NFEAT; k0 += 32) {
#pragma unroll
        for (int p = 0; p < 2; p++) {
            int r  = (tid >> 3) + p * 32;       // tile row 0..63
            int cv = (tid & 7) * 4;             // k-offset 0..28
            float4 v = make_float4(0.f, 0.f, 0.f, 0.f);
            int gm = m0 + r;
            if (gm < M) v = *(const float4*)&x[(size_t)gm * NFEAT + k0 + cv];
            As[cv + 0][r] = v.x;
            As[cv + 1][r] = v.y;
            As[cv + 2][r] = v.z;
            As[cv + 3][r] = v.w;
        }
#pragma unroll
        for (int p = 0; p < 2; p++) {
            int r  = (tid >> 4) + p * 16;       // 0..31
            int cv = (tid & 15) * 4;            // 0..60
            *(float4*)&Bs[r][cv] = *(const float4*)&W[(size_t)(k0 + r) * NHID + cv];
        }
        __syncthreads();

#pragma unroll
        for (int k = 0; k < 32; k++) {
            float4 a = *(const float4*)&As[k][ty * 4];
            float4 b = *(const float4*)&Bs[k][tx * 4];
            float av[4] = {a.x, a.y, a.z, a.w};
            float bv[4] = {b.x, b.y, b.z, b.w};
#pragma unroll
            for (int i = 0; i < 4; i++)
#pragma unroll
                for (int j = 0; j < 4; j++) acc[i][j] += av[i] * bv[j];
        }
        __syncthreads();
    }

#pragma unroll
    for (int i = 0; i < 4; i++) {
        int row = m0 + ty * 4 + i;
        if (row < M) {
            float4 v = make_float4(acc[i][0], acc[i][1], acc[i][2], acc[i][3]);
            *(float4*)&g_Wh[(size_t)row * NHID + tx * 4] = v;
        }
    }
}

// ---------------- kernel 2: per-node scores si, sj ----------------
__global__ void score_kernel(const float* __restrict__ aw, int M) {
    int n = blockIdx.x * blockDim.x + threadIdx.x;
    if (n >= M) return;
    const float4* w4 = (const float4*)&g_Wh[(size_t)n * NHID];
    const float4* a4 = (const float4*)aw;          // a_w[0:64]
    const float4* b4 = a4 + (NHID / 4);            // a_w[64:128]
    float si = 0.f, sj = 0.f;
#pragma unroll
    for (int i = 0; i < NHID / 4; i++) {
        float4 v = w4[i];
        float4 a = __ldg(&a4[i]);
        float4 b = __ldg(&b4[i]);
        si += v.x * a.x + v.y * a.y + v.z * a.z + v.w * a.w;
        sj += v.x * b.x + v.y * b.y + v.z * b.z + v.w * b.w;
    }
    g_si[n] = si;
    g_sj[n] = sj;
}

// ---------------- kernel 3: edge pass A: h + hsum scatter ----------------
__global__ void edgeA_kernel(const void* __restrict__ ei,
                             const float* __restrict__ ab, int E, int M) {
    int e = blockIdx.x * blockDim.x + threadIdx.x;
    if (e >= E) return;
    const int is64 = g_idx64;
    int s = load_idx(ei, e, is64, M);
    int d = load_idx(ei, (size_t)E + e, is64, M);
    float sc = g_si[s] + g_sj[d] + __ldg(&ab[0]);
    float l  = sc > 0.f ? sc : NEG_SLOPE * sc;
    float h  = expf(l);
    g_h[e] = h;
    atomicAdd(&g_hsum[s], h);
}

// ---------------- kernel 3.5: reciprocal of h_sum ----------------
__global__ void recip_kernel(int M) {
    int n = blockIdx.x * blockDim.x + threadIdx.x;
    if (n >= M) return;
    g_hsum[n] = __frcp_rn(g_hsum[n]);
}

// ---------------- kernel 4: edge pass B: alpha + weighted scatter --------
// 16 threads per edge, each does one float4 (red.global.add.v4.f32).
__global__ void edgeB_kernel(const void* __restrict__ ei,
                             float* __restrict__ out,
                             float* __restrict__ alpha_out, int E, int M) {
    long long gt = (long long)blockIdx.x * blockDim.x + threadIdx.x;
    int e    = (int)(gt >> 4);
    int part = (int)(gt & 15);
    if (e >= E) return;
    const int is64 = g_idx64;
    int s = load_idx(ei, e, is64, M);
    int d = load_idx(ei, (size_t)E + e, is64, M);
    float alpha = g_h[e] * g_hsum[s];        // hsum holds reciprocal
    if (part == 0 && alpha_out) alpha_out[e] = alpha;
    float4 w = *(const float4*)&g_Wh[(size_t)d * NHID + part * 4];
    float* dst = &out[(size_t)s * NHID + part * 4];
    asm volatile("red.global.add.v4.f32 [%0], {%1,%2,%3,%4};"
                 :: "l"(dst),
                    "f"(w.x * alpha), "f"(w.y * alpha),
                    "f"(w.z * alpha), "f"(w.w * alpha)
                 : "memory");
}

// ---------------- launch ----------------
extern "C" void kernel_launch(void* const* d_in, const int* in_sizes, int n_in,
                              void* d_out, int out_size) {
    const float* x  = (const float*)d_in[0];
    const float* W  = (const float*)d_in[1];
    const float* aw = (const float*)d_in[2];
    const float* ab = (const float*)d_in[3];
    const void*  ei = d_in[4];

    const int M = in_sizes[0] / NFEAT;       // 100000
    const int E = in_sizes[4] / 2;           // 1600000 (element count same for i32/i64)

    float* out       = (float*)d_out;                    // [M, 64]
    // alpha only if the output buffer actually has room for it
    float* alpha_out = (out_size >= M * NHID + E) ? out + (size_t)M * NHID : nullptr;

    detect_kernel<<<1, 256>>>(ei, E, M);
    {
        int total = M * (NHID / 4);          // float4 count
        zero_kernel<<<(total + 255) / 256, 256>>>((float4*)out, M);
    }
    gemm_kernel<<<(M + 63) / 64, 256>>>(x, W, M);
    score_kernel<<<(M + 255) / 256, 256>>>(aw, M);
    edgeA_kernel<<<(E + 255) / 256, 256>>>(ei, ab, E, M);
    recip_kernel<<<(M + 255) / 256, 256>>>(M);
    {
        long long total = (long long)E * 16;
        edgeB_kernel<<<(int)((total + 255) / 256), 256>>>(ei, out, alpha_out, E, M);
    }
}